// round 5
// baseline (speedup 1.0000x reference)
#include <cuda_runtime.h>
#include <cstdint>

// BoundaryOperator: out[r,:] += val * feat[c,:]  (SpMM, D=64 fp32)
// Fixed-stride binning with 4B packed entries (values are +/-1; non-+/-1
// values go to a tagged overflow list), then gather with slab prefetch and
// streaming output write. Overflow handled inline by the owning gather warp.

#define D_FEAT   64
#define K_MAX    16              // slots per row (64B slab of packed uint)
#define NV_CAP   524288          // max output rows supported by bin path
#define OVF_CAP  1048576         // overflow entries
#define CNT_MASK 0x3FFFFFFF
#define OVF_FLAG 0x40000000

__device__ int  g_counts[NV_CAP];                       // count | OVF_FLAG
__device__ unsigned g_bins[(size_t)NV_CAP * K_MAX];     // (col<<1)|neg
__device__ int4 g_ovf[OVF_CAP];                         // {row, col, valbits, 0}
__device__ int  g_ovf_count;

// ---------------- kernels ----------------

__global__ void zero_counts_kernel(int n) {
    int i = blockIdx.x * blockDim.x + threadIdx.x;
    if (i < n) g_counts[i] = 0;
    if (i == 0) g_ovf_count = 0;
}

__global__ __launch_bounds__(256) void bin_kernel(
    const int*   __restrict__ rows,
    const int*   __restrict__ cols,
    const float* __restrict__ vals,
    int nnz)
{
    int i = blockIdx.x * blockDim.x + threadIdx.x;
    if (i >= nnz) return;
    int   r = __ldcs(&rows[i]);     // read-once streams: don't pollute L2
    int   c = __ldcs(&cols[i]);
    float v = __ldcs(&vals[i]);

    if (v == 1.0f || v == -1.0f) {
        int slot = atomicAdd(&g_counts[r], 1) & CNT_MASK;
        if (slot < K_MAX) {
            g_bins[(size_t)r * K_MAX + slot] =
                ((unsigned)c << 1) | (v < 0.0f ? 1u : 0u);
        } else {
            int o = atomicAdd(&g_ovf_count, 1);
            if (o < OVF_CAP) g_ovf[o] = make_int4(r, c, __float_as_int(v), 0);
        }
    } else {
        // general value: overflow list + tag the row so gather scans it
        atomicOr(&g_counts[r], OVF_FLAG);
        int o = atomicAdd(&g_ovf_count, 1);
        if (o < OVF_CAP) g_ovf[o] = make_int4(r, c, __float_as_int(v), 0);
    }
}

// one warp per output row; lane owns a float2 (32 lanes x 8B = 256B row).
// Slab (64B) prefetched by lanes 0..15, broadcast via shuffle; the up-to-16
// feature LDGs are independent (high MLP). Rare flagged rows also scan the
// overflow list before the single streaming write.
__global__ __launch_bounds__(256) void gather_kernel(
    const float2* __restrict__ feat2,   // [NUM_E * 32]
    float2*       __restrict__ out2,    // [num_v * 32]
    int num_v)
{
    int warp = (blockIdx.x * blockDim.x + threadIdx.x) >> 5;
    int lane = threadIdx.x & 31;
    if (warp >= num_v) return;

    int raw = g_counts[warp];                       // broadcast load
    int cnt = raw & CNT_MASK;
    bool scan_ovf = (raw & OVF_FLAG) || (cnt > K_MAX);
    int n = cnt > K_MAX ? K_MAX : cnt;

    // one coalesced 64B slab read: lane j (<16) holds entry j
    unsigned mine = 0;
    if (lane < n) mine = g_bins[(size_t)warp * K_MAX + lane];

    // broadcast packed entries to all lanes (fixed-count, fully unrolled)
    unsigned es[K_MAX];
    #pragma unroll
    for (int j = 0; j < K_MAX; j++)
        es[j] = __shfl_sync(0xffffffffu, mine, j);

    // predicated, unrolled: all feature loads independent -> MLP = n
    float2 acc = make_float2(0.f, 0.f);
    #pragma unroll
    for (int j = 0; j < K_MAX; j++) {
        if (j < n) {
            unsigned e = es[j];
            float2 f = feat2[(size_t)(e >> 1) * 32 + lane];
            float v = (e & 1u) ? -1.0f : 1.0f;
            acc.x = fmaf(v, f.x, acc.x);
            acc.y = fmaf(v, f.y, acc.y);
        }
    }

    if (scan_ovf) {                                  // rare path
        int total = g_ovf_count;
        if (total > OVF_CAP) total = OVF_CAP;
        for (int i = 0; i < total; i++) {
            int4 e = g_ovf[i];
            if (e.x == warp) {
                float v = __int_as_float(e.z);
                float2 f = feat2[(size_t)e.y * 32 + lane];
                acc.x = fmaf(v, f.x, acc.x);
                acc.y = fmaf(v, f.y, acc.y);
            }
        }
    }

    // streaming (evict-first) full-line write: keep features/bins in L2
    float2* p = out2 + (size_t)warp * 32 + lane;
    asm volatile("st.global.cs.v2.f32 [%0], {%1, %2};"
                 :: "l"(p), "f"(acc.x), "f"(acc.y) : "memory");
}

// ---------------- fallback (proven R1 atomic path) ----------------

__global__ void zero_out_kernel(float4* __restrict__ out4, int n4) {
    int i = blockIdx.x * blockDim.x + threadIdx.x;
    if (i < n4) out4[i] = make_float4(0.f, 0.f, 0.f, 0.f);
}

__global__ __launch_bounds__(256) void spmm_scatter_kernel(
    const float4* __restrict__ feat4, const float* __restrict__ vals,
    const int* __restrict__ rows, const int* __restrict__ cols,
    float* __restrict__ out, int nnz)
{
    int i = blockIdx.x * blockDim.x + threadIdx.x;
    int e = i >> 4;
    if (e >= nnz) return;
    int chunk = i & 15;
    int   r = rows[e];
    int   c = cols[e];
    float v = vals[e];
    float4 f = feat4[(size_t)c * 16 + chunk];
    float* p = out + (size_t)r * D_FEAT + chunk * 4;
    asm volatile("red.global.add.v4.f32 [%0], {%1, %2, %3, %4};"
                 :: "l"(p), "f"(v * f.x), "f"(v * f.y), "f"(v * f.z), "f"(v * f.w)
                 : "memory");
}

extern "C" void kernel_launch(void* const* d_in, const int* in_sizes, int n_in,
                              void* d_out, int out_size) {
    const float* feat = (const float*)d_in[0];
    const float* vals = (const float*)d_in[1];
    const int*   rows = (const int*)  d_in[2];
    const int*   cols = (const int*)  d_in[3];
    float*       out  = (float*)      d_out;

    int nnz   = in_sizes[1];
    int num_v = out_size / D_FEAT;

    if (num_v > NV_CAP || num_v <= 0 || nnz <= 0) {
        int n4 = out_size / 4;
        zero_out_kernel<<<(n4 + 255) / 256, 256>>>((float4*)out, n4);
        if (nnz > 0) {
            long long total = (long long)nnz * 16;
            spmm_scatter_kernel<<<(int)((total + 255) / 256), 256>>>(
                (const float4*)feat, vals, rows, cols, out, nnz);
        }
        return;
    }

    zero_counts_kernel<<<(num_v + 255) / 256, 256>>>(num_v);
    bin_kernel<<<(nnz + 255) / 256, 256>>>(rows, cols, vals, nnz);

    long long gthreads = (long long)num_v * 32;
    gather_kernel<<<(int)((gthreads + 255) / 256), 256>>>(
        (const float2*)feat, (float2*)out, num_v);
}

// round 7
// speedup vs baseline: 1.1268x; 1.1268x over previous
#include <cuda_runtime.h>
#include <cstdint>

// BoundaryOperator: out[r,:] += val * feat[c,:]  (SpMM, D=64 fp32)
// R4 structure (proven 222us): fixed-stride int2 binning -> gather with slab
// prefetch + shuffle broadcast (high MLP) + streaming output write.
// Delta vs R4: overflow handled inline by the owning gather warp (kills the
// 10us do-nothing overflow kernel); zero_counts vectorized.

#define D_FEAT   64
#define K_MAX    16            // slots per row (128B slab of int2)
#define NV_CAP   524288        // max output rows supported by bin path
#define OVF_CAP  1048576       // overflow entries

__device__ int  g_counts[NV_CAP];
__device__ int2 g_bins[(size_t)NV_CAP * K_MAX];   // {col, float_bits(val)}
__device__ int4 g_ovf[OVF_CAP];                   // {row, col, valbits, pad}
__device__ int  g_ovf_count;

// ---------------- kernels ----------------

__global__ void zero_counts_kernel(int n4) {   // n4 = ceil(num_v/4)
    int i = blockIdx.x * blockDim.x + threadIdx.x;
    if (i < n4) ((int4*)g_counts)[i] = make_int4(0, 0, 0, 0);
    if (i == 0) g_ovf_count = 0;
}

__global__ __launch_bounds__(256) void bin_kernel(
    const int*   __restrict__ rows,
    const int*   __restrict__ cols,
    const float* __restrict__ vals,
    int nnz)
{
    int i = blockIdx.x * blockDim.x + threadIdx.x;
    if (i >= nnz) return;
    int   r  = __ldcs(&rows[i]);        // read-once streams: don't pollute L2
    int   c  = __ldcs(&cols[i]);
    float v  = __ldcs(&vals[i]);
    int slot = atomicAdd(&g_counts[r], 1);
    if (slot < K_MAX) {
        g_bins[(size_t)r * K_MAX + slot] = make_int2(c, __float_as_int(v));
    } else {
        int o = atomicAdd(&g_ovf_count, 1);
        if (o < OVF_CAP) g_ovf[o] = make_int4(r, c, __float_as_int(v), 0);
    }
}

// one warp per output row; lane owns a float2 (32 lanes x 8B = 256B row).
// Slab is prefetched by one coalesced load + shuffles so the up-to-16
// feature LDGs are independent (high MLP), then accumulated. Rows with
// count > K_MAX (rare) also scan the overflow list before the store.
__global__ __launch_bounds__(256) void gather_kernel(
    const float2* __restrict__ feat2,   // [NUM_E * 32]
    float2*       __restrict__ out2,    // [num_v * 32]
    int num_v)
{
    int warp = (blockIdx.x * blockDim.x + threadIdx.x) >> 5;
    int lane = threadIdx.x & 31;
    if (warp >= num_v) return;

    int cnt = g_counts[warp];            // broadcast load
    int n = cnt > K_MAX ? K_MAX : cnt;
    const int2* slab = &g_bins[(size_t)warp * K_MAX];

    // one coalesced 128B slab read: lane j holds entry j
    int2 mine = make_int2(0, 0);
    if (lane < n) mine = slab[lane];

    // broadcast entries to all lanes (fixed-count, fully unrolled)
    int   cs[K_MAX];
    float vs[K_MAX];
    #pragma unroll
    for (int j = 0; j < K_MAX; j++) {
        cs[j] = __shfl_sync(0xffffffffu, mine.x, j);
        vs[j] = __int_as_float(__shfl_sync(0xffffffffu, mine.y, j));
    }

    // predicated, unrolled: all feature loads independent -> MLP = n
    float2 acc = make_float2(0.f, 0.f);
    #pragma unroll
    for (int j = 0; j < K_MAX; j++) {
        if (j < n) {
            float2 f = feat2[(size_t)cs[j] * 32 + lane];
            acc.x = fmaf(vs[j], f.x, acc.x);
            acc.y = fmaf(vs[j], f.y, acc.y);
        }
    }

    if (cnt > K_MAX) {                   // rare: scan overflow list inline
        int total = g_ovf_count;
        if (total > OVF_CAP) total = OVF_CAP;
        for (int i = 0; i < total; i++) {
            int4 e = g_ovf[i];
            if (e.x == warp) {
                float v = __int_as_float(e.z);
                float2 f = feat2[(size_t)e.y * 32 + lane];
                acc.x = fmaf(v, f.x, acc.x);
                acc.y = fmaf(v, f.y, acc.y);
            }
        }
    }

    // streaming (evict-first) full-line write: keep features/bins in L2
    float2* p = out2 + (size_t)warp * 32 + lane;
    asm volatile("st.global.cs.v2.f32 [%0], {%1, %2};"
                 :: "l"(p), "f"(acc.x), "f"(acc.y) : "memory");
}

// ---------------- fallback (proven R1 atomic path) ----------------

__global__ void zero_out_kernel(float4* __restrict__ out4, int n4) {
    int i = blockIdx.x * blockDim.x + threadIdx.x;
    if (i < n4) out4[i] = make_float4(0.f, 0.f, 0.f, 0.f);
}

__global__ __launch_bounds__(256) void spmm_scatter_kernel(
    const float4* __restrict__ feat4, const float* __restrict__ vals,
    const int* __restrict__ rows, const int* __restrict__ cols,
    float* __restrict__ out, int nnz)
{
    int i = blockIdx.x * blockDim.x + threadIdx.x;
    int e = i >> 4;
    if (e >= nnz) return;
    int chunk = i & 15;
    int   r = rows[e];
    int   c = cols[e];
    float v = vals[e];
    float4 f = feat4[(size_t)c * 16 + chunk];
    float* p = out + (size_t)r * D_FEAT + chunk * 4;
    asm volatile("red.global.add.v4.f32 [%0], {%1, %2, %3, %4};"
                 :: "l"(p), "f"(v * f.x), "f"(v * f.y), "f"(v * f.z), "f"(v * f.w)
                 : "memory");
}

extern "C" void kernel_launch(void* const* d_in, const int* in_sizes, int n_in,
                              void* d_out, int out_size) {
    const float* feat = (const float*)d_in[0];
    const float* vals = (const float*)d_in[1];
    const int*   rows = (const int*)  d_in[2];
    const int*   cols = (const int*)  d_in[3];
    float*       out  = (float*)      d_out;

    int nnz   = in_sizes[1];
    int num_v = out_size / D_FEAT;

    if (num_v > NV_CAP || num_v <= 0 || nnz <= 0 || (num_v & 3) != 0) {
        int n4 = out_size / 4;
        zero_out_kernel<<<(n4 + 255) / 256, 256>>>((float4*)out, n4);
        if (nnz > 0) {
            long long total = (long long)nnz * 16;
            spmm_scatter_kernel<<<(int)((total + 255) / 256), 256>>>(
                (const float4*)feat, vals, rows, cols, out, nnz);
        }
        return;
    }

    zero_counts_kernel<<<(num_v / 4 + 255) / 256, 256>>>(num_v / 4);
    bin_kernel<<<(nnz + 255) / 256, 256>>>(rows, cols, vals, nnz);

    long long gthreads = (long long)num_v * 32;
    gather_kernel<<<(int)((gthreads + 255) / 256), 256>>>(
        (const float2*)feat, (float2*)out, num_v);
}

// round 9
// speedup vs baseline: 1.1827x; 1.0495x over previous
#include <cuda_runtime.h>
#include <cstdint>

// BoundaryOperator: out[r,:] += val * feat[c,:]  (SpMM, D=64 fp32)
// Fixed-stride int2 binning -> gather with slab prefetch + shuffle broadcast
// (high MLP) + streaming output write. Overflow handled inline.
// R7 delta: slab read is UNCONDITIONAL (independent of the count load) so the
// count and slab LDGs issue in parallel — cuts one L2 round trip off the
// per-warp dependency chain. Count/slab reads use evict-first (.cs).

#define D_FEAT   64
#define K_MAX    16            // slots per row (128B slab of int2)
#define NV_CAP   524288        // max output rows supported by bin path
#define OVF_CAP  1048576       // overflow entries

__device__ int  g_counts[NV_CAP];
__device__ int2 g_bins[(size_t)NV_CAP * K_MAX];   // {col, float_bits(val)}
__device__ int4 g_ovf[OVF_CAP];                   // {row, col, valbits, pad}
__device__ int  g_ovf_count;

// ---------------- kernels ----------------

__global__ void zero_counts_kernel(int n4) {   // n4 = num_v/4
    int i = blockIdx.x * blockDim.x + threadIdx.x;
    if (i < n4) ((int4*)g_counts)[i] = make_int4(0, 0, 0, 0);
    if (i == 0) g_ovf_count = 0;
}

__global__ __launch_bounds__(256) void bin_kernel(
    const int*   __restrict__ rows,
    const int*   __restrict__ cols,
    const float* __restrict__ vals,
    int nnz)
{
    int i = blockIdx.x * blockDim.x + threadIdx.x;
    if (i >= nnz) return;
    int   r  = __ldcs(&rows[i]);        // read-once streams: don't pollute L2
    int   c  = __ldcs(&cols[i]);
    float v  = __ldcs(&vals[i]);
    int slot = atomicAdd(&g_counts[r], 1);
    if (slot < K_MAX) {
        g_bins[(size_t)r * K_MAX + slot] = make_int2(c, __float_as_int(v));
    } else {
        int o = atomicAdd(&g_ovf_count, 1);
        if (o < OVF_CAP) g_ovf[o] = make_int4(r, c, __float_as_int(v), 0);
    }
}

// one warp per output row; lane owns a float2 (32 lanes x 8B = 256B row).
__global__ __launch_bounds__(256) void gather_kernel(
    const float2* __restrict__ feat2,   // [NUM_E * 32]
    float2*       __restrict__ out2,    // [num_v * 32]
    int num_v)
{
    int warp = (blockIdx.x * blockDim.x + threadIdx.x) >> 5;
    int lane = threadIdx.x & 31;
    if (warp >= num_v) return;

    // Independent loads: count and full slab issue together (no serialization).
    int cnt = __ldcs(&g_counts[warp]);   // broadcast, read-once
    int2 mine = make_int2(0, 0);
    if (lane < K_MAX)                    // NOT dependent on cnt
        mine = __ldcs(&g_bins[(size_t)warp * K_MAX + lane]);

    int n = cnt > K_MAX ? K_MAX : cnt;

    // broadcast entries to all lanes (fixed-count, fully unrolled)
    int   cs[K_MAX];
    float vs[K_MAX];
    #pragma unroll
    for (int j = 0; j < K_MAX; j++) {
        cs[j] = __shfl_sync(0xffffffffu, mine.x, j);
        vs[j] = __int_as_float(__shfl_sync(0xffffffffu, mine.y, j));
    }

    // predicated, unrolled: all feature loads independent -> MLP = n
    // (garbage entries j >= n never dereferenced)
    float2 acc = make_float2(0.f, 0.f);
    #pragma unroll
    for (int j = 0; j < K_MAX; j++) {
        if (j < n) {
            float2 f = feat2[(size_t)cs[j] * 32 + lane];
            acc.x = fmaf(vs[j], f.x, acc.x);
            acc.y = fmaf(vs[j], f.y, acc.y);
        }
    }

    if (cnt > K_MAX) {                   // rare: scan overflow list inline
        int total = g_ovf_count;
        if (total > OVF_CAP) total = OVF_CAP;
        for (int i = 0; i < total; i++) {
            int4 e = g_ovf[i];
            if (e.x == warp) {
                float v = __int_as_float(e.z);
                float2 f = feat2[(size_t)e.y * 32 + lane];
                acc.x = fmaf(v, f.x, acc.x);
                acc.y = fmaf(v, f.y, acc.y);
            }
        }
    }

    // streaming (evict-first) full-line write: keep features in L2
    float2* p = out2 + (size_t)warp * 32 + lane;
    asm volatile("st.global.cs.v2.f32 [%0], {%1, %2};"
                 :: "l"(p), "f"(acc.x), "f"(acc.y) : "memory");
}

// ---------------- fallback (proven R1 atomic path) ----------------

__global__ void zero_out_kernel(float4* __restrict__ out4, int n4) {
    int i = blockIdx.x * blockDim.x + threadIdx.x;
    if (i < n4) out4[i] = make_float4(0.f, 0.f, 0.f, 0.f);
}

__global__ __launch_bounds__(256) void spmm_scatter_kernel(
    const float4* __restrict__ feat4, const float* __restrict__ vals,
    const int* __restrict__ rows, const int* __restrict__ cols,
    float* __restrict__ out, int nnz)
{
    int i = blockIdx.x * blockDim.x + threadIdx.x;
    int e = i >> 4;
    if (e >= nnz) return;
    int chunk = i & 15;
    int   r = rows[e];
    int   c = cols[e];
    float v = vals[e];
    float4 f = feat4[(size_t)c * 16 + chunk];
    float* p = out + (size_t)r * D_FEAT + chunk * 4;
    asm volatile("red.global.add.v4.f32 [%0], {%1, %2, %3, %4};"
                 :: "l"(p), "f"(v * f.x), "f"(v * f.y), "f"(v * f.z), "f"(v * f.w)
                 : "memory");
}

extern "C" void kernel_launch(void* const* d_in, const int* in_sizes, int n_in,
                              void* d_out, int out_size) {
    const float* feat = (const float*)d_in[0];
    const float* vals = (const float*)d_in[1];
    const int*   rows = (const int*)  d_in[2];
    const int*   cols = (const int*)  d_in[3];
    float*       out  = (float*)      d_out;

    int nnz   = in_sizes[1];
    int num_v = out_size / D_FEAT;

    if (num_v > NV_CAP || num_v <= 0 || nnz <= 0 || (num_v & 3) != 0) {
        int n4 = out_size / 4;
        zero_out_kernel<<<(n4 + 255) / 256, 256>>>((float4*)out, n4);
        if (nnz > 0) {
            long long total = (long long)nnz * 16;
            spmm_scatter_kernel<<<(int)((total + 255) / 256), 256>>>(
                (const float4*)feat, vals, rows, cols, out, nnz);
        }
        return;
    }

    zero_counts_kernel<<<(num_v / 4 + 255) / 256, 256>>>(num_v / 4);
    bin_kernel<<<(nnz + 255) / 256, 256>>>(rows, cols, vals, nnz);

    long long gthreads = (long long)num_v * 32;
    gather_kernel<<<(int)((gthreads + 255) / 256), 256>>>(
        (const float2*)feat, (float2*)out, num_v);
}